// round 13
// baseline (speedup 1.0000x reference)
#include <cuda_runtime.h>
#include <cuda_bf16.h>

// Wasserstein CT cost-matrix mean.
// Algebraic identity: mean(matrix) = 2(C-1)/C^2 * mean(|ct|).
// Per pixel, sum_{c,l} |1{t==l} - 1{q==c}| = 2(C-1) regardless of t,q.
// So only ct matters: result = 2(C-1)/(C^2*N) * sum(|ct|).
//
// CONVERGED scheme (record draw: 4.54us kernel / 6.21us total; identical-
// source redraws span 4.54-5.38us kernel / 6.21-8.67us total -> envelope
// noise dominates every remaining candidate edit):
// - 128 CTAs x 256 threads: 1 CTA/SM on 128 SMs, exactly 2 front-batched
//   float4 loads/thread -> single exposed load round (measured-best shape;
//   32x256, 128x128, and 2-kernel variants all measured slower).
// - Block reduce: shfl tree + 1 bar + pairwise smem fold (depth-3).
// - Tail: ONE u64 fixed-point atomic per block packs the partial sum
//   (bits [8:64), 2^-24 units) with an arrival counter (bits [0:8)).
//   Integer adds commute -> bit-deterministic for any arrival order. The
//   last block's thread 0 reads the complete sum from the atomic return
//   (zero extra global reads), writes the scalar, resets for graph replay.

#define RED_BLOCKS 128
#define RED_THREADS 256
#define UNROLL 2
#define FIX_SCALE 16777216.0f          // 2^24
#define FIX_INV   (1.0 / 16777216.0)

__device__ unsigned long long g_acc;   // zero-init; reset by last block

__device__ __forceinline__ float warp_reduce_sum(float v) {
    #pragma unroll
    for (int off = 16; off > 0; off >>= 1)
        v += __shfl_xor_sync(0xFFFFFFFFu, v, off);
    return v;
}

__global__ void __launch_bounds__(RED_THREADS)
abs_mean_fused(const float* __restrict__ ct, int n, float scale,
               float* __restrict__ out) {
    __shared__ float s_warp[RED_THREADS / 32];   // 8 warp sums

    const int tid = threadIdx.x;
    const int gtid = blockIdx.x * RED_THREADS + tid;
    const int nthreads = RED_BLOCKS * RED_THREADS;   // 32768

    const int nv4 = n >> 2;
    const float4* __restrict__ ct4 = reinterpret_cast<const float4*>(ct);

    float acc = 0.0f;

    // Fast path: n = 512*512 -> exactly 2 front-batched float4 loads/thread.
    if (nv4 == nthreads * UNROLL) {
        float4 v0 = ct4[gtid];
        float4 v1 = ct4[gtid + nthreads];
        acc  = fabsf(v0.x) + fabsf(v0.y) + fabsf(v0.z) + fabsf(v0.w);
        acc += fabsf(v1.x) + fabsf(v1.y) + fabsf(v1.z) + fabsf(v1.w);
    } else {
        // Robust grid-stride path for other sizes.
        for (int i = gtid; i < nv4; i += nthreads) {
            float4 v = ct4[i];
            acc += fabsf(v.x) + fabsf(v.y) + fabsf(v.z) + fabsf(v.w);
        }
        if (gtid == 0) {
            for (int i = nv4 << 2; i < n; i++) acc += fabsf(ct[i]);
        }
    }

    // Warp reduction (float shfl tree), warp sums to smem.
    acc = warp_reduce_sum(acc);
    if ((tid & 31) == 0) s_warp[tid >> 5] = acc;
    __syncthreads();

    if (tid == 0) {
        // 8-warp fold as a pairwise tree (dep depth 3 FADDs).
        float a01 = s_warp[0] + s_warp[1];
        float a23 = s_warp[2] + s_warp[3];
        float a45 = s_warp[4] + s_warp[5];
        float a67 = s_warp[6] + s_warp[7];
        float v = (a01 + a23) + (a45 + a67);

        // Pack: fixed-point partial in bits [8:64), arrival count in [0:8).
        // |ct| >= 0 so the fixed value is non-negative; 128 arrivals < 256
        // so the count never carries into the sum field.
        unsigned long long contrib =
            (((unsigned long long)__float2ll_rn(v * FIX_SCALE)) << 8) | 1ull;

        unsigned long long old = atomicAdd(&g_acc, contrib);

        if ((old & 0xFFull) == (unsigned long long)(RED_BLOCKS - 1)) {
            // Last arrival: old + contrib is the complete packed total.
            unsigned long long total = (old + contrib) >> 8;
            out[0] = (float)((double)total * FIX_INV) * scale;
            g_acc = 0ull;  // restore for next graph replay
        }
    }
}

extern "C" void kernel_launch(void* const* d_in, const int* in_sizes, int n_in,
                              void* d_out, int out_size) {
    // Inputs (metadata order): pred_stage1 [1,C,H,W] f32, ct [1,H,W] f32,
    // target [1,1,H,W] i64. Only ct is needed (see identity above).
    const float* ct = (const float*)d_in[1];
    const int n = in_sizes[1];                      // H*W
    const int C = (n > 0) ? (in_sizes[0] / n) : 1;  // class count from pred size

    const double scale_d = (2.0 * (double)(C - 1)) /
                           ((double)C * (double)C * (double)n);
    const float scale = (float)scale_d;

    abs_mean_fused<<<RED_BLOCKS, RED_THREADS>>>(ct, n, scale, (float*)d_out);
}

// round 14
// speedup vs baseline: 1.0047x; 1.0047x over previous
#include <cuda_runtime.h>
#include <cuda_bf16.h>

// Wasserstein CT cost-matrix mean.
// Algebraic identity: mean(matrix) = 2(C-1)/C^2 * mean(|ct|).
// Per pixel, sum_{c,l} |1{t==l} - 1{q==c}| = 2(C-1) regardless of t,q.
// So only ct matters: result = 2(C-1)/(C^2*N) * sum(|ct|).
//
// CONVERGED scheme (record draw: 4.54us kernel / 6.21us total; identical-
// source redraws span 4.54-5.38us kernel / 6.21-8.67us total -> envelope
// noise dominates every remaining candidate edit):
// - 128 CTAs x 256 threads: 1 CTA/SM on 128 SMs, exactly 2 front-batched
//   float4 loads/thread -> single exposed load round (measured-best shape;
//   32x256, 128x128, and 2-kernel variants all measured slower).
// - Block reduce: shfl tree + 1 bar + pairwise smem fold (depth-3).
// - Tail: ONE u64 fixed-point atomic per block packs the partial sum
//   (bits [8:64), 2^-24 units) with an arrival counter (bits [0:8)).
//   Integer adds commute -> bit-deterministic for any arrival order. The
//   last block's thread 0 reads the complete sum from the atomic return
//   (zero extra global reads), writes the scalar, resets for graph replay.

#define RED_BLOCKS 128
#define RED_THREADS 256
#define UNROLL 2
#define FIX_SCALE 16777216.0f          // 2^24
#define FIX_INV   (1.0 / 16777216.0)

__device__ unsigned long long g_acc;   // zero-init; reset by last block

__device__ __forceinline__ float warp_reduce_sum(float v) {
    #pragma unroll
    for (int off = 16; off > 0; off >>= 1)
        v += __shfl_xor_sync(0xFFFFFFFFu, v, off);
    return v;
}

__global__ void __launch_bounds__(RED_THREADS)
abs_mean_fused(const float* __restrict__ ct, int n, float scale,
               float* __restrict__ out) {
    __shared__ float s_warp[RED_THREADS / 32];   // 8 warp sums

    const int tid = threadIdx.x;
    const int gtid = blockIdx.x * RED_THREADS + tid;
    const int nthreads = RED_BLOCKS * RED_THREADS;   // 32768

    const int nv4 = n >> 2;
    const float4* __restrict__ ct4 = reinterpret_cast<const float4*>(ct);

    float acc = 0.0f;

    // Fast path: n = 512*512 -> exactly 2 front-batched float4 loads/thread.
    if (nv4 == nthreads * UNROLL) {
        float4 v0 = ct4[gtid];
        float4 v1 = ct4[gtid + nthreads];
        acc  = fabsf(v0.x) + fabsf(v0.y) + fabsf(v0.z) + fabsf(v0.w);
        acc += fabsf(v1.x) + fabsf(v1.y) + fabsf(v1.z) + fabsf(v1.w);
    } else {
        // Robust grid-stride path for other sizes.
        for (int i = gtid; i < nv4; i += nthreads) {
            float4 v = ct4[i];
            acc += fabsf(v.x) + fabsf(v.y) + fabsf(v.z) + fabsf(v.w);
        }
        if (gtid == 0) {
            for (int i = nv4 << 2; i < n; i++) acc += fabsf(ct[i]);
        }
    }

    // Warp reduction (float shfl tree), warp sums to smem.
    acc = warp_reduce_sum(acc);
    if ((tid & 31) == 0) s_warp[tid >> 5] = acc;
    __syncthreads();

    if (tid == 0) {
        // 8-warp fold as a pairwise tree (dep depth 3 FADDs).
        float a01 = s_warp[0] + s_warp[1];
        float a23 = s_warp[2] + s_warp[3];
        float a45 = s_warp[4] + s_warp[5];
        float a67 = s_warp[6] + s_warp[7];
        float v = (a01 + a23) + (a45 + a67);

        // Pack: fixed-point partial in bits [8:64), arrival count in [0:8).
        // |ct| >= 0 so the fixed value is non-negative; 128 arrivals < 256
        // so the count never carries into the sum field.
        unsigned long long contrib =
            (((unsigned long long)__float2ll_rn(v * FIX_SCALE)) << 8) | 1ull;

        unsigned long long old = atomicAdd(&g_acc, contrib);

        if ((old & 0xFFull) == (unsigned long long)(RED_BLOCKS - 1)) {
            // Last arrival: old + contrib is the complete packed total.
            unsigned long long total = (old + contrib) >> 8;
            out[0] = (float)((double)total * FIX_INV) * scale;
            g_acc = 0ull;  // restore for next graph replay
        }
    }
}

extern "C" void kernel_launch(void* const* d_in, const int* in_sizes, int n_in,
                              void* d_out, int out_size) {
    // Inputs (metadata order): pred_stage1 [1,C,H,W] f32, ct [1,H,W] f32,
    // target [1,1,H,W] i64. Only ct is needed (see identity above).
    const float* ct = (const float*)d_in[1];
    const int n = in_sizes[1];                      // H*W
    const int C = (n > 0) ? (in_sizes[0] / n) : 1;  // class count from pred size

    const double scale_d = (2.0 * (double)(C - 1)) /
                           ((double)C * (double)C * (double)n);
    const float scale = (float)scale_d;

    abs_mean_fused<<<RED_BLOCKS, RED_THREADS>>>(ct, n, scale, (float*)d_out);
}

// round 15
// speedup vs baseline: 1.0386x; 1.0338x over previous
#include <cuda_runtime.h>
#include <cuda_bf16.h>

// Wasserstein CT cost-matrix mean.
// Algebraic identity: mean(matrix) = 2(C-1)/C^2 * mean(|ct|).
// Per pixel, sum_{c,l} |1{t==l} - 1{q==c}| = 2(C-1) regardless of t,q.
// So only ct matters: result = 2(C-1)/(C^2*N) * sum(|ct|).
//
// CONVERGED scheme (record draw: 4.54us kernel / 6.21us total; identical-
// source redraws span 4.54-5.38us kernel / 6.21-8.67us total -> envelope
// noise dominates every remaining candidate edit):
// - 128 CTAs x 256 threads: 1 CTA/SM on 128 SMs, exactly 2 front-batched
//   float4 loads/thread -> single exposed load round (measured-best shape;
//   32x256, 128x128, and 2-kernel variants all measured slower).
// - Block reduce: shfl tree + 1 bar + pairwise smem fold (depth-3).
// - Tail: ONE u64 fixed-point atomic per block packs the partial sum
//   (bits [8:64), 2^-24 units) with an arrival counter (bits [0:8)).
//   Integer adds commute -> bit-deterministic for any arrival order. The
//   last block's thread 0 reads the complete sum from the atomic return
//   (zero extra global reads), writes the scalar, resets for graph replay.

#define RED_BLOCKS 128
#define RED_THREADS 256
#define UNROLL 2
#define FIX_SCALE 16777216.0f          // 2^24
#define FIX_INV   (1.0 / 16777216.0)

__device__ unsigned long long g_acc;   // zero-init; reset by last block

__device__ __forceinline__ float warp_reduce_sum(float v) {
    #pragma unroll
    for (int off = 16; off > 0; off >>= 1)
        v += __shfl_xor_sync(0xFFFFFFFFu, v, off);
    return v;
}

__global__ void __launch_bounds__(RED_THREADS)
abs_mean_fused(const float* __restrict__ ct, int n, float scale,
               float* __restrict__ out) {
    __shared__ float s_warp[RED_THREADS / 32];   // 8 warp sums

    const int tid = threadIdx.x;
    const int gtid = blockIdx.x * RED_THREADS + tid;
    const int nthreads = RED_BLOCKS * RED_THREADS;   // 32768

    const int nv4 = n >> 2;
    const float4* __restrict__ ct4 = reinterpret_cast<const float4*>(ct);

    float acc = 0.0f;

    // Fast path: n = 512*512 -> exactly 2 front-batched float4 loads/thread.
    if (nv4 == nthreads * UNROLL) {
        float4 v0 = ct4[gtid];
        float4 v1 = ct4[gtid + nthreads];
        acc  = fabsf(v0.x) + fabsf(v0.y) + fabsf(v0.z) + fabsf(v0.w);
        acc += fabsf(v1.x) + fabsf(v1.y) + fabsf(v1.z) + fabsf(v1.w);
    } else {
        // Robust grid-stride path for other sizes.
        for (int i = gtid; i < nv4; i += nthreads) {
            float4 v = ct4[i];
            acc += fabsf(v.x) + fabsf(v.y) + fabsf(v.z) + fabsf(v.w);
        }
        if (gtid == 0) {
            for (int i = nv4 << 2; i < n; i++) acc += fabsf(ct[i]);
        }
    }

    // Warp reduction (float shfl tree), warp sums to smem.
    acc = warp_reduce_sum(acc);
    if ((tid & 31) == 0) s_warp[tid >> 5] = acc;
    __syncthreads();

    if (tid == 0) {
        // 8-warp fold as a pairwise tree (dep depth 3 FADDs).
        float a01 = s_warp[0] + s_warp[1];
        float a23 = s_warp[2] + s_warp[3];
        float a45 = s_warp[4] + s_warp[5];
        float a67 = s_warp[6] + s_warp[7];
        float v = (a01 + a23) + (a45 + a67);

        // Pack: fixed-point partial in bits [8:64), arrival count in [0:8).
        // |ct| >= 0 so the fixed value is non-negative; 128 arrivals < 256
        // so the count never carries into the sum field.
        unsigned long long contrib =
            (((unsigned long long)__float2ll_rn(v * FIX_SCALE)) << 8) | 1ull;

        unsigned long long old = atomicAdd(&g_acc, contrib);

        if ((old & 0xFFull) == (unsigned long long)(RED_BLOCKS - 1)) {
            // Last arrival: old + contrib is the complete packed total.
            unsigned long long total = (old + contrib) >> 8;
            out[0] = (float)((double)total * FIX_INV) * scale;
            g_acc = 0ull;  // restore for next graph replay
        }
    }
}

extern "C" void kernel_launch(void* const* d_in, const int* in_sizes, int n_in,
                              void* d_out, int out_size) {
    // Inputs (metadata order): pred_stage1 [1,C,H,W] f32, ct [1,H,W] f32,
    // target [1,1,H,W] i64. Only ct is needed (see identity above).
    const float* ct = (const float*)d_in[1];
    const int n = in_sizes[1];                      // H*W
    const int C = (n > 0) ? (in_sizes[0] / n) : 1;  // class count from pred size

    const double scale_d = (2.0 * (double)(C - 1)) /
                           ((double)C * (double)C * (double)n);
    const float scale = (float)scale_d;

    abs_mean_fused<<<RED_BLOCKS, RED_THREADS>>>(ct, n, scale, (float*)d_out);
}

// round 16
// speedup vs baseline: 1.0539x; 1.0147x over previous
#include <cuda_runtime.h>
#include <cuda_bf16.h>

// Wasserstein CT cost-matrix mean.
// Algebraic identity: mean(matrix) = 2(C-1)/C^2 * mean(|ct|).
// Per pixel, sum_{c,l} |1{t==l} - 1{q==c}| = 2(C-1) regardless of t,q.
// So only ct matters: result = 2(C-1)/(C^2*N) * sum(|ct|).
//
// CONVERGED scheme (record draw: 4.54us kernel / 6.21us total; identical-
// source redraws span 4.54-5.38us kernel / 6.21-8.67us total -> envelope
// noise dominates every remaining candidate edit):
// - 128 CTAs x 256 threads: 1 CTA/SM on 128 SMs, exactly 2 front-batched
//   float4 loads/thread -> single exposed load round (measured-best shape;
//   32x256, 128x128, and 2-kernel variants all measured slower).
// - Block reduce: shfl tree + 1 bar + pairwise smem fold (depth-3).
// - Tail: ONE u64 fixed-point atomic per block packs the partial sum
//   (bits [8:64), 2^-24 units) with an arrival counter (bits [0:8)).
//   Integer adds commute -> bit-deterministic for any arrival order. The
//   last block's thread 0 reads the complete sum from the atomic return
//   (zero extra global reads), writes the scalar, resets for graph replay.

#define RED_BLOCKS 128
#define RED_THREADS 256
#define UNROLL 2
#define FIX_SCALE 16777216.0f          // 2^24
#define FIX_INV   (1.0 / 16777216.0)

__device__ unsigned long long g_acc;   // zero-init; reset by last block

__device__ __forceinline__ float warp_reduce_sum(float v) {
    #pragma unroll
    for (int off = 16; off > 0; off >>= 1)
        v += __shfl_xor_sync(0xFFFFFFFFu, v, off);
    return v;
}

__global__ void __launch_bounds__(RED_THREADS)
abs_mean_fused(const float* __restrict__ ct, int n, float scale,
               float* __restrict__ out) {
    __shared__ float s_warp[RED_THREADS / 32];   // 8 warp sums

    const int tid = threadIdx.x;
    const int gtid = blockIdx.x * RED_THREADS + tid;
    const int nthreads = RED_BLOCKS * RED_THREADS;   // 32768

    const int nv4 = n >> 2;
    const float4* __restrict__ ct4 = reinterpret_cast<const float4*>(ct);

    float acc = 0.0f;

    // Fast path: n = 512*512 -> exactly 2 front-batched float4 loads/thread.
    if (nv4 == nthreads * UNROLL) {
        float4 v0 = ct4[gtid];
        float4 v1 = ct4[gtid + nthreads];
        acc  = fabsf(v0.x) + fabsf(v0.y) + fabsf(v0.z) + fabsf(v0.w);
        acc += fabsf(v1.x) + fabsf(v1.y) + fabsf(v1.z) + fabsf(v1.w);
    } else {
        // Robust grid-stride path for other sizes.
        for (int i = gtid; i < nv4; i += nthreads) {
            float4 v = ct4[i];
            acc += fabsf(v.x) + fabsf(v.y) + fabsf(v.z) + fabsf(v.w);
        }
        if (gtid == 0) {
            for (int i = nv4 << 2; i < n; i++) acc += fabsf(ct[i]);
        }
    }

    // Warp reduction (float shfl tree), warp sums to smem.
    acc = warp_reduce_sum(acc);
    if ((tid & 31) == 0) s_warp[tid >> 5] = acc;
    __syncthreads();

    if (tid == 0) {
        // 8-warp fold as a pairwise tree (dep depth 3 FADDs).
        float a01 = s_warp[0] + s_warp[1];
        float a23 = s_warp[2] + s_warp[3];
        float a45 = s_warp[4] + s_warp[5];
        float a67 = s_warp[6] + s_warp[7];
        float v = (a01 + a23) + (a45 + a67);

        // Pack: fixed-point partial in bits [8:64), arrival count in [0:8).
        // |ct| >= 0 so the fixed value is non-negative; 128 arrivals < 256
        // so the count never carries into the sum field.
        unsigned long long contrib =
            (((unsigned long long)__float2ll_rn(v * FIX_SCALE)) << 8) | 1ull;

        unsigned long long old = atomicAdd(&g_acc, contrib);

        if ((old & 0xFFull) == (unsigned long long)(RED_BLOCKS - 1)) {
            // Last arrival: old + contrib is the complete packed total.
            unsigned long long total = (old + contrib) >> 8;
            out[0] = (float)((double)total * FIX_INV) * scale;
            g_acc = 0ull;  // restore for next graph replay
        }
    }
}

extern "C" void kernel_launch(void* const* d_in, const int* in_sizes, int n_in,
                              void* d_out, int out_size) {
    // Inputs (metadata order): pred_stage1 [1,C,H,W] f32, ct [1,H,W] f32,
    // target [1,1,H,W] i64. Only ct is needed (see identity above).
    const float* ct = (const float*)d_in[1];
    const int n = in_sizes[1];                      // H*W
    const int C = (n > 0) ? (in_sizes[0] / n) : 1;  // class count from pred size

    const double scale_d = (2.0 * (double)(C - 1)) /
                           ((double)C * (double)C * (double)n);
    const float scale = (float)scale_d;

    abs_mean_fused<<<RED_BLOCKS, RED_THREADS>>>(ct, n, scale, (float*)d_out);
}